// round 10
// baseline (speedup 1.0000x reference)
#include <cuda_runtime.h>
#include <cuda_fp16.h>
#include <cstdint>

#define NROI 4000
#define CCH  64
#define FH   240
#define FW   240
#define NPIX (FH*FW)
#define NBT  (NPIX / 64)   // 900 transpose blocks

// ---------------- scratch (no allocations allowed) ----------------
__device__ __align__(16) __half2 g_fmTh[NPIX * 32];   // HWC fp16 fm (7.4 MB)
__device__ __align__(16) __half  g_pooledh[3 * NROI * CCH]; // pooled feats fp16 [scale][row][64]
__device__ __align__(16) __half  g_hh[3 * NROI * CCH];      // head outputs fp16 [scale][row][64]
__device__ float g_gpart[NBT * CCH];       // per-block channel partial sums
__device__ float g_bp1eff[128];            // bp1 + head(g) @ P1[192:256]
// fp16 transposed weights, [n][k] layout (B col-major fragments)
__device__ __align__(16) __half g_W1t[128 * 64];
__device__ __align__(16) __half g_W2t[64 * 128];
__device__ __align__(16) __half g_P1t[128 * 192];
__device__ __align__(16) __half g_P2t[64 * 128];

// ---------------- mma.sync m16n8k16 f16 -> f32 ----------------
__device__ __forceinline__ void mma_f16(float* c,
                                        unsigned a0, unsigned a1, unsigned a2, unsigned a3,
                                        unsigned b0, unsigned b1) {
    asm volatile(
        "mma.sync.aligned.m16n8k16.row.col.f32.f16.f16.f32 "
        "{%0,%1,%2,%3}, {%4,%5,%6,%7}, {%8,%9}, {%0,%1,%2,%3};\n"
        : "+f"(c[0]), "+f"(c[1]), "+f"(c[2]), "+f"(c[3])
        : "r"(a0), "r"(a1), "r"(a2), "r"(a3), "r"(b0), "r"(b1));
}

// ---------------- 0) convert weights to fp16 [n][k] ----------------
__global__ void prep_weights(const float* __restrict__ W1, const float* __restrict__ W2,
                             const float* __restrict__ P1, const float* __restrict__ P2) {
    int idx = blockIdx.x * 256 + threadIdx.x;
    if (idx < 8192) {                       // W1t[128][64]
        int n = idx >> 6, k = idx & 63;
        g_W1t[idx] = __float2half(W1[k * 128 + n]);
    } else if (idx < 16384) {               // W2t[64][128]
        int i = idx - 8192;
        int n = i >> 7, k = i & 127;
        g_W2t[i] = __float2half(W2[k * 64 + n]);
    } else if (idx < 40960) {               // P1t[128][192]  (k<192 only)
        int i = idx - 16384;
        int n = i / 192, k = i - n * 192;
        g_P1t[i] = __float2half(P1[k * 128 + n]);
    } else if (idx < 49152) {               // P2t[64][128]
        int i = idx - 40960;
        int n = i >> 7, k = i & 127;
        g_P2t[i] = __float2half(P2[k * 64 + n]);
    }
}

// ---------------- 1) transpose CHW fp32 -> HWC fp16 + channel partial sums ----------------
__global__ void transpose_kernel(const float* __restrict__ fm) {
    __shared__ float tile[64][65];
    int pix0 = blockIdx.x * 64;
    int tid  = threadIdx.x;
    int lane = tid & 63;
    int grp  = tid >> 6;
    #pragma unroll
    for (int c = grp; c < 64; c += 4)
        tile[c][lane] = fm[c * NPIX + pix0 + lane];
    __syncthreads();
    int c2 = tid & 31;
    int pg = tid >> 5;
    #pragma unroll
    for (int p = pg; p < 64; p += 8)
        g_fmTh[(pix0 + p) * 32 + c2] =
            __floats2half2_rn(tile[2 * c2][p], tile[2 * c2 + 1][p]);
    if (tid < 64) {
        float s = 0.f;
        #pragma unroll 16
        for (int p = 0; p < 64; p++) s += tile[tid][p];
        g_gpart[blockIdx.x * 64 + tid] = s;
    }
}

// ---------------- 2) reduce gmean + fold head(g) into bp1 ----------------
__global__ void head_const_kernel(const float* __restrict__ W1, const float* __restrict__ b1,
                                  const float* __restrict__ W2, const float* __restrict__ b2,
                                  const float* __restrict__ P1, const float* __restrict__ bp1) {
    __shared__ float gs[64];
    __shared__ float part[2][64];
    __shared__ float t[128];
    __shared__ float hg[64];
    int tid = threadIdx.x;  // 128 threads
    {
        int ch = tid & 63;
        int half = tid >> 6;
        int b0 = half * (NBT / 2);
        int b1e = b0 + (NBT / 2);
        float s = 0.f;
        for (int b = b0; b < b1e; b++) s += g_gpart[b * 64 + ch];
        part[half][ch] = s;
    }
    __syncthreads();
    if (tid < 64)
        gs[tid] = (part[0][tid] + part[1][tid]) * (1.0f / (float)NPIX);
    __syncthreads();
    float a = b1[tid];
    #pragma unroll 8
    for (int c = 0; c < 64; c++) a = fmaf(gs[c], W1[c * 128 + tid], a);
    t[tid] = fmaxf(a, 0.f);
    __syncthreads();
    if (tid < 64) {
        float a2 = b2[tid];
        #pragma unroll 8
        for (int k = 0; k < 128; k++) a2 = fmaf(t[k], W2[k * 64 + tid], a2);
        hg[tid] = fmaxf(a2, 0.f);
    }
    __syncthreads();
    float be = bp1[tid];
    #pragma unroll 8
    for (int c = 0; c < 64; c++) be = fmaf(hg[c], P1[(192 + c) * 128 + tid], be);
    g_bp1eff[tid] = be;
}

// ---------------- 3) pooling: 4 samples/warp-iter, HFMA2 bilinear -> fp16 out ----------------
template<int S>
__device__ __forceinline__ void pool_roi_v(int n, int lane,
                                           const float* __restrict__ boxes,
                                           __half* __restrict__ outb) {
    constexpr int SS = S * S;
    int sub = lane >> 3;
    int cl  = lane & 7;

    float bx1 = __ldg(&boxes[n * 4 + 0]);
    float by1 = __ldg(&boxes[n * 4 + 1]);
    float bx2 = __ldg(&boxes[n * 4 + 2]);
    float by2 = __ldg(&boxes[n * 4 + 3]);
    float nx1 = bx1 * (2.0f / 960.0f) - 1.0f;
    float ny1 = by1 * (2.0f / 960.0f) - 1.0f;
    float nx2 = bx2 * (2.0f / 960.0f) - 1.0f;
    float ny2 = by2 * (2.0f / 960.0f) - 1.0f;
    float cx = (nx1 + nx2) * 0.5f;
    float cy = (ny1 + ny2) * 0.5f;
    float w  = fmaxf(nx2 - nx1, 1e-6f);
    float h  = fmaxf(ny2 - ny1, 1e-6f);
    float stepx = w * (120.0f / (float)S);
    float stepy = h * (120.0f / (float)S);
    float ixb = fmaf(w * 60.0f, (1.0f / (float)S - 1.0f), fmaf(cx, 120.0f, 119.5f));
    float iyb = fmaf(h * 60.0f, (1.0f / (float)S - 1.0f), fmaf(cy, 120.0f, 119.5f));

    float acc[8];
    #pragma unroll
    for (int k = 0; k < 8; k++) acc[k] = 0.f;

    const uint4* fm4 = (const uint4*)g_fmTh;

    #pragma unroll 2
    for (int base = 0; base < SS; base += 4) {
        int samp = base + sub;
        bool alive = (samp < SS);
        int sc = alive ? samp : 0;
        int i = sc / S;
        int j = sc - i * S;
        float ix = fmaf((float)j, stepx, ixb);
        float iy = fmaf((float)i, stepy, iyb);
        float x0f = floorf(ix), y0f = floorf(iy);
        float dx = ix - x0f, dy = iy - y0f;
        int x0 = (int)x0f, y0 = (int)y0f;
        int x1 = x0 + 1,   y1 = y0 + 1;
        float wx0 = ((unsigned)x0 < FW) ? (1.f - dx) : 0.f;
        float wx1 = ((unsigned)x1 < FW) ? dx : 0.f;
        float wy0 = (alive && (unsigned)y0 < FH) ? (1.f - dy) : 0.f;
        float wy1 = (alive && (unsigned)y1 < FH) ? dy : 0.f;
        int xc0 = max(0, min(x0, FW - 1));
        int xc1 = max(0, min(x1, FW - 1));
        int yc0 = max(0, min(y0, FH - 1));
        int yc1 = max(0, min(y1, FH - 1));
        int r0 = yc0 * FW, r1 = yc1 * FW;
        uint4 q00 = __ldg(&fm4[(r0 + xc0) * 8 + cl]);
        uint4 q01 = __ldg(&fm4[(r0 + xc1) * 8 + cl]);
        uint4 q10 = __ldg(&fm4[(r1 + xc0) * 8 + cl]);
        uint4 q11 = __ldg(&fm4[(r1 + xc1) * 8 + cl]);
        __half2 h00 = __float2half2_rn(wy0 * wx0);
        __half2 h01 = __float2half2_rn(wy0 * wx1);
        __half2 h10 = __float2half2_rn(wy1 * wx0);
        __half2 h11 = __float2half2_rn(wy1 * wx1);
        const __half2* f00 = (const __half2*)&q00;
        const __half2* f01 = (const __half2*)&q01;
        const __half2* f10 = (const __half2*)&q10;
        const __half2* f11 = (const __half2*)&q11;
        #pragma unroll
        for (int k = 0; k < 4; k++) {
            __half2 s = __hmul2(h00, f00[k]);
            s = __hfma2(h01, f01[k], s);
            s = __hfma2(h10, f10[k], s);
            s = __hfma2(h11, f11[k], s);
            float2 fs = __half22float2(s);
            acc[2 * k]     += fs.x;
            acc[2 * k + 1] += fs.y;
        }
    }

    #pragma unroll
    for (int k = 0; k < 8; k++) {
        acc[k] += __shfl_down_sync(0xffffffffu, acc[k], 16);
        acc[k] += __shfl_down_sync(0xffffffffu, acc[k], 8);
    }
    if (sub == 0) {
        const float inv = 1.0f / (float)SS;
        __half2 p[4];
        #pragma unroll
        for (int k = 0; k < 4; k++)
            p[k] = __floats2half2_rn(acc[2 * k] * inv, acc[2 * k + 1] * inv);
        *(uint4*)&outb[(size_t)n * 64 + cl * 8] = *(uint4*)p;
    }
}

// LPT ordering: heavy S=11 tasks first, S=3 last.
__global__ void pool_all_kernel(const float* __restrict__ boxes) {
    int tid  = threadIdx.x;
    int lane = tid & 31;
    int warp = tid >> 5;
    int task = blockIdx.x * 8 + warp;
    if (task < NROI) {
        pool_roi_v<11>(task, lane, boxes, g_pooledh + (size_t)2 * NROI * CCH);
    } else if (task < 2 * NROI) {
        pool_roi_v<7>(task - NROI, lane, boxes, g_pooledh + (size_t)NROI * CCH);
    } else {
        pool_roi_v<3>(task - 2 * NROI, lane, boxes, g_pooledh);
    }
}

// ---------------- 4) head via tensor cores ----------------
// 32 rows/block, 256 thr (8 warps). Phase A: T=relu(X@W1+b1) [32x128] -> smem fp16.
// Phase B: H=relu(T@W2+b2) [32x64] -> g_hh fp16.
#define TS_STRIDE 136   // halves; 272B row stride -> conflict-free banks
__global__ __launch_bounds__(256)
void head_mma_kernel(const float* __restrict__ b1, const float* __restrict__ b2) {
    __shared__ __half Tsh[32 * TS_STRIDE];
    int tid  = threadIdx.x;
    int w    = tid >> 5;
    int lane = tid & 31;
    int g    = lane >> 2;
    int tig  = lane & 3;
    int scale = blockIdx.y;
    int row0  = blockIdx.x * 32;
    const __half* X = g_pooledh + (size_t)scale * NROI * CCH;

    int mt    = w & 1;
    int rloc  = mt * 16 + g;            // local row (and +8)
    int r_lo  = row0 + rloc;

    // ---- phase A: 2 mtiles x 16 ntiles; warp: mt, 4 ntiles at nbase ----
    int nbase = (w >> 1) * 32;
    float c[4][4];
    #pragma unroll
    for (int j = 0; j < 4; j++)
        #pragma unroll
        for (int q = 0; q < 4; q++) c[j][q] = 0.f;

    #pragma unroll
    for (int k0 = 0; k0 < 64; k0 += 16) {
        const __half* ar = X + (size_t)r_lo * 64 + k0 + 2 * tig;
        unsigned a0 = *(const unsigned*)ar;
        unsigned a1 = *(const unsigned*)(ar + 8 * 64);
        unsigned a2 = *(const unsigned*)(ar + 8);
        unsigned a3 = *(const unsigned*)(ar + 8 * 64 + 8);
        #pragma unroll
        for (int j = 0; j < 4; j++) {
            const __half* bp = g_W1t + (nbase + j * 8 + g) * 64 + k0 + 2 * tig;
            unsigned b0 = *(const unsigned*)bp;
            unsigned b1r = *(const unsigned*)(bp + 8);
            mma_f16(c[j], a0, a1, a2, a3, b0, b1r);
        }
    }
    #pragma unroll
    for (int j = 0; j < 4; j++) {
        int col = nbase + j * 8 + 2 * tig;
        float2 bb = *(const float2*)&b1[col];
        __half2 lo = __floats2half2_rn(fmaxf(c[j][0] + bb.x, 0.f),
                                       fmaxf(c[j][1] + bb.y, 0.f));
        __half2 hi = __floats2half2_rn(fmaxf(c[j][2] + bb.x, 0.f),
                                       fmaxf(c[j][3] + bb.y, 0.f));
        *(__half2*)&Tsh[rloc * TS_STRIDE + col] = lo;
        *(__half2*)&Tsh[(rloc + 8) * TS_STRIDE + col] = hi;
    }
    __syncthreads();

    // ---- phase B: 2 mtiles x 8 ntiles; warp: mt, 2 ntiles at nb2 ----
    int nb2 = (w >> 1) * 16;
    float d[2][4];
    #pragma unroll
    for (int j = 0; j < 2; j++)
        #pragma unroll
        for (int q = 0; q < 4; q++) d[j][q] = 0.f;

    #pragma unroll
    for (int k0 = 0; k0 < 128; k0 += 16) {
        const __half* ar = &Tsh[rloc * TS_STRIDE + k0 + 2 * tig];
        unsigned a0 = *(const unsigned*)ar;
        unsigned a1 = *(const unsigned*)(ar + 8 * TS_STRIDE);
        unsigned a2 = *(const unsigned*)(ar + 8);
        unsigned a3 = *(const unsigned*)(ar + 8 * TS_STRIDE + 8);
        #pragma unroll
        for (int j = 0; j < 2; j++) {
            const __half* bp = g_W2t + (nb2 + j * 8 + g) * 128 + k0 + 2 * tig;
            unsigned b0 = *(const unsigned*)bp;
            unsigned b1r = *(const unsigned*)(bp + 8);
            mma_f16(d[j], a0, a1, a2, a3, b0, b1r);
        }
    }
    __half* Hout = g_hh + (size_t)scale * NROI * CCH;
    #pragma unroll
    for (int j = 0; j < 2; j++) {
        int col = nb2 + j * 8 + 2 * tig;
        float2 bb = *(const float2*)&b2[col];
        __half2 lo = __floats2half2_rn(fmaxf(d[j][0] + bb.x, 0.f),
                                       fmaxf(d[j][1] + bb.y, 0.f));
        __half2 hi = __floats2half2_rn(fmaxf(d[j][2] + bb.x, 0.f),
                                       fmaxf(d[j][3] + bb.y, 0.f));
        *(__half2*)&Hout[(size_t)r_lo * 64 + col] = lo;
        *(__half2*)&Hout[(size_t)(r_lo + 8) * 64 + col] = hi;
    }
}

// ---------------- 5) final via tensor cores ----------------
// Phase 1: T=relu(cat(h)@P1 + bp1eff) [32x128], K=192 over 3 g_hh chunks.
// Phase 2: out=relu(T@P2 + bp2) [32x64] fp32.
__global__ __launch_bounds__(256)
void final_mma_kernel(const float* __restrict__ bp2, float* __restrict__ out) {
    __shared__ __half Tsh[32 * TS_STRIDE];
    int tid  = threadIdx.x;
    int w    = tid >> 5;
    int lane = tid & 31;
    int g    = lane >> 2;
    int tig  = lane & 3;
    int row0 = blockIdx.x * 32;

    int mt   = w & 1;
    int rloc = mt * 16 + g;
    int r_lo = row0 + rloc;

    int nbase = (w >> 1) * 32;
    float c[4][4];
    #pragma unroll
    for (int j = 0; j < 4; j++)
        #pragma unroll
        for (int q = 0; q < 4; q++) c[j][q] = 0.f;

    #pragma unroll
    for (int k0 = 0; k0 < 192; k0 += 16) {
        int chunk = k0 >> 6;
        int kin = k0 & 63;
        const __half* ar = g_hh + (size_t)chunk * NROI * CCH
                         + (size_t)r_lo * 64 + kin + 2 * tig;
        unsigned a0 = *(const unsigned*)ar;
        unsigned a1 = *(const unsigned*)(ar + 8 * 64);
        unsigned a2 = *(const unsigned*)(ar + 8);
        unsigned a3 = *(const unsigned*)(ar + 8 * 64 + 8);
        #pragma unroll
        for (int j = 0; j < 4; j++) {
            const __half* bp = g_P1t + (nbase + j * 8 + g) * 192 + k0 + 2 * tig;
            unsigned b0 = *(const unsigned*)bp;
            unsigned b1r = *(const unsigned*)(bp + 8);
            mma_f16(c[j], a0, a1, a2, a3, b0, b1r);
        }
    }
    #pragma unroll
    for (int j = 0; j < 4; j++) {
        int col = nbase + j * 8 + 2 * tig;
        float2 bb = *(const float2*)&g_bp1eff[col];
        __half2 lo = __floats2half2_rn(fmaxf(c[j][0] + bb.x, 0.f),
                                       fmaxf(c[j][1] + bb.y, 0.f));
        __half2 hi = __floats2half2_rn(fmaxf(c[j][2] + bb.x, 0.f),
                                       fmaxf(c[j][3] + bb.y, 0.f));
        *(__half2*)&Tsh[rloc * TS_STRIDE + col] = lo;
        *(__half2*)&Tsh[(rloc + 8) * TS_STRIDE + col] = hi;
    }
    __syncthreads();

    int nb2 = (w >> 1) * 16;
    float d[2][4];
    #pragma unroll
    for (int j = 0; j < 2; j++)
        #pragma unroll
        for (int q = 0; q < 4; q++) d[j][q] = 0.f;

    #pragma unroll
    for (int k0 = 0; k0 < 128; k0 += 16) {
        const __half* ar = &Tsh[rloc * TS_STRIDE + k0 + 2 * tig];
        unsigned a0 = *(const unsigned*)ar;
        unsigned a1 = *(const unsigned*)(ar + 8 * TS_STRIDE);
        unsigned a2 = *(const unsigned*)(ar + 8);
        unsigned a3 = *(const unsigned*)(ar + 8 * TS_STRIDE + 8);
        #pragma unroll
        for (int j = 0; j < 2; j++) {
            const __half* bp = g_P2t + (nb2 + j * 8 + g) * 128 + k0 + 2 * tig;
            unsigned b0 = *(const unsigned*)bp;
            unsigned b1r = *(const unsigned*)(bp + 8);
            mma_f16(d[j], a0, a1, a2, a3, b0, b1r);
        }
    }
    #pragma unroll
    for (int j = 0; j < 2; j++) {
        int col = nb2 + j * 8 + 2 * tig;
        float2 bb = *(const float2*)&bp2[col];
        float2 lo, hi;
        lo.x = fmaxf(d[j][0] + bb.x, 0.f);
        lo.y = fmaxf(d[j][1] + bb.y, 0.f);
        hi.x = fmaxf(d[j][2] + bb.x, 0.f);
        hi.y = fmaxf(d[j][3] + bb.y, 0.f);
        *(float2*)&out[(size_t)r_lo * 64 + col] = lo;
        *(float2*)&out[(size_t)(r_lo + 8) * 64 + col] = hi;
    }
}

// ---------------- launch ----------------
extern "C" void kernel_launch(void* const* d_in, const int* in_sizes, int n_in,
                              void* d_out, int out_size) {
    const float* fm    = (const float*)d_in[0];
    const float* boxes = (const float*)d_in[1];
    const float* W1    = (const float*)d_in[2];
    const float* b1    = (const float*)d_in[3];
    const float* W2    = (const float*)d_in[4];
    const float* b2    = (const float*)d_in[5];
    const float* P1    = (const float*)d_in[6];
    const float* bp1   = (const float*)d_in[7];
    const float* P2    = (const float*)d_in[8];
    const float* bp2   = (const float*)d_in[9];
    float* out = (float*)d_out;

    prep_weights<<<192, 256>>>(W1, W2, P1, P2);
    transpose_kernel<<<NBT, 256>>>(fm);
    head_const_kernel<<<1, 128>>>(W1, b1, W2, b2, P1, bp1);

    const int PB = (3 * NROI) / 8;  // 1500 blocks
    pool_all_kernel<<<PB, 256>>>(boxes);

    dim3 hgrid(NROI / 32, 3);       // 125 x 3 blocks
    head_mma_kernel<<<hgrid, 256>>>(b1, b2);

    final_mma_kernel<<<NROI / 32, 256>>>(bp2, out);
}